// round 12
// baseline (speedup 1.0000x reference)
#include <cuda_runtime.h>

// x:      (4, 64, 128, 128) fp32  -> 256 independent 128x128 images
// weight: (4, 576, 128, 128) fp32 -> 9 taps per channel, tap k strided by H*W
// steps = 8
//
// R9 champion architecture (62.3us): persistent CTAs (1/SM), 512 thr, V=2
// (warp owns region rows 2g,2g+1 in registers), smem ping-pong, packed
// fma.rn.f32x2 stencil, cp.async.bulk staging prefetched one tile ahead
// (10 issuer warps), scalar prologue (the packed one regressed twice).
// Round 12 deltas (additive, mechanism-independent):
//  - own-row laterals via clamped scalar LDS (like neighbor rows) instead of
//    post-FMA shfl: removes the 4xSHFL(26cyc)+pk tail before each STS/barrier;
//    post-barrier the 16 register-ready fma2 cover the LDS latency
//  - dynamic tile scheduling via a global atomic ticket (reset kernel each
//    launch): makespan tracks the average SM instead of 14-tile worst case

#define H      128
#define W      128
#define IMG    (H * W)
#define STEPS  8
#define TH     16
#define NT     2048
#define SROWS  34
#define RROWS  32

#define OFF_MBAR 0
#define OFF_TKT  16
#define OFF_BUF  1024
#define OFF_WS   (OFF_BUF + 2 * SROWS * W * 4)   // 1024 + 34816  = 35840
#define OFF_XS   (OFF_WS + 9 * RROWS * W * 4)    // + 147456      = 183296
#define SMEM_TOTAL (OFF_XS + RROWS * W * 4)      // + 16384       = 199680

typedef unsigned long long u64;
typedef unsigned int u32;

__device__ u32 g_ticket;

__global__ void reset_ticket_kernel() { g_ticket = 0u; }

__device__ __forceinline__ u32 s2u(const void* p) {
    u32 a;
    asm("{ .reg .u64 t; cvta.to.shared.u64 t, %1; cvt.u32.u64 %0, t; }"
        : "=r"(a) : "l"(p));
    return a;
}
__device__ __forceinline__ u64 pk(float lo, float hi) {
    u64 r; asm("mov.b64 %0, {%1,%2};" : "=l"(r) : "f"(lo), "f"(hi)); return r;
}
__device__ __forceinline__ void upk(u64 v, float& lo, float& hi) {
    asm("mov.b64 {%0,%1}, %2;" : "=f"(lo), "=f"(hi) : "l"(v));
}
__device__ __forceinline__ void fma2(u64& d, u64 a, u64 b) {
    asm("fma.rn.f32x2 %0, %1, %2, %0;" : "+l"(d) : "l"(a), "l"(b));
}
__device__ __forceinline__ u64 mul2(u64 a, u64 b) {
    u64 d; asm("mul.rn.f32x2 %0, %1, %2;" : "=l"(d) : "l"(a), "l"(b)); return d;
}

__device__ __forceinline__ void mbar_wait(u32 mbar, u32 parity) {
    asm volatile(
        "{\n\t.reg .pred P;\n\t"
        "W_%=:\n\t"
        "mbarrier.try_wait.parity.shared::cta.b64 P, [%0], %1, 0x989680;\n\t"
        "@P bra.uni D_%=;\n\t"
        "bra.uni W_%=;\n\t"
        "D_%=:\n\t}"
        :: "r"(mbar), "r"(parity) : "memory");
}
__device__ __forceinline__ void bulk_g2s(u32 dst, const void* src, u32 bytes, u32 mbar) {
    asm volatile(
        "cp.async.bulk.shared::cluster.global.mbarrier::complete_tx::bytes "
        "[%0], [%1], %2, [%3];"
        :: "r"(dst), "l"(src), "r"(bytes), "r"(mbar) : "memory");
}

// Distributed prefetch: issuer k (0..8 = weight tap k, 9 = x); mbar count 10.
__device__ __forceinline__ void issue_prefetch_k(int t, int k,
                                                 const float* x, const float* wgt,
                                                 u32 ws, u32 xs, u32 mbar) {
    const int img = t >> 3;
    const int t0  = (t & 7) * TH;
    const int rlo = (t0 - 8 < 0) ? 0 : (t0 - 8);
    const int rhi = (t0 + 24 > H) ? H : (t0 + 24);
    const int nrows = rhi - rlo;
    const int droff = rlo - (t0 - 8);
    const u32 bytes = (u32)nrows * (W * 4);
    asm volatile("mbarrier.arrive.expect_tx.shared.b64 _, [%0], %1;"
                 :: "r"(mbar), "r"(bytes) : "memory");
    if (k < 9) {
        const float* src = wgt + ((size_t)(img * 9 + k) << 14) + rlo * W;
        bulk_g2s(ws + (u32)(k * RROWS + droff) * (W * 4), src, bytes, mbar);
    } else {
        bulk_g2s(xs + (u32)droff * (W * 4), x + ((size_t)img << 14) + rlo * W, bytes, mbar);
    }
}

__global__ __launch_bounds__(512, 1)
void diffusion_persist_kernel(const float* __restrict__ x,
                              const float* __restrict__ wgt,
                              float* __restrict__ out)
{
    extern __shared__ char smem[];
    float (*buf)[SROWS][W] = (float (*)[SROWS][W])(smem + OFF_BUF);
    const float* wsp = (const float*)(smem + OFF_WS);
    const float* xsp = (const float*)(smem + OFF_XS);
    volatile u32* tkt = (volatile u32*)(smem + OFF_TKT);
    const u32 mbar = s2u(smem + OFF_MBAR);
    const u32 ws_a = s2u(smem + OFF_WS);
    const u32 xs_a = s2u(smem + OFF_XS);

    const int tid  = threadIdx.x;
    const int lane = tid & 31;
    const int warp = tid >> 5;          // 0..15; owns region rows 2g, 2g+1
    const int col0 = lane << 2;
    const int g2   = warp * 2;
    // clamped lateral columns: the clamped lanes hit zeroed weights
    const int colL = (lane == 0)  ? col0     : col0 - 1;
    const int colR = (lane == 31) ? col0 + 3 : col0 + 4;
    const bool issuer = (lane == 0 && warp < 10);

    // one-time init: guard rows (region rows -1 and 32 -> zero forever), mbar
    if (tid < 128) {
        int b = tid >> 6, rr = ((tid >> 5) & 1) ? (SROWS - 1) : 0;
        *(float4*)&buf[b][rr][(tid & 31) << 2] = make_float4(0.f, 0.f, 0.f, 0.f);
    }
    if (tid == 0) {
        asm volatile("mbarrier.init.shared.b64 [%0], 10;" :: "r"(mbar) : "memory");
        *tkt = atomicAdd(&g_ticket, 1u);
    }
    __syncthreads();

    int t = (int)*tkt;
    if (issuer && t < NT) issue_prefetch_k(t, warp, x, wgt, ws_a, xs_a, mbar);
    u32 ph = 0;

    while (t < NT) {
        mbar_wait(mbar, ph); ph ^= 1u;
        if (tid == 0) *tkt = atomicAdd(&g_ticket, 1u);  // next tile ticket

        const int img = t >> 3;
        const int t0  = (t & 7) * TH;

        // ---- tile prologue (R9 scalar form): staging -> normalized packed regs
        u64 Wp[2][3][6];
        float4 y0, y1;
#pragma unroll
        for (int ro = 0; ro < 2; ro++) {
            const int rr   = g2 + ro;
            const int grow = t0 - 8 + rr;
            const bool rv  = ((unsigned)grow < (unsigned)H);
            float aa[9][4];
            if (rv) {
                float s0 = 0.f, s1 = 0.f, s2 = 0.f, s3 = 0.f;
#pragma unroll
                for (int k = 0; k < 9; k++) {
                    float4 tv = *(const float4*)&wsp[(k * RROWS + rr) * W + col0];
                    aa[k][0] = fabsf(tv.x); aa[k][1] = fabsf(tv.y);
                    aa[k][2] = fabsf(tv.z); aa[k][3] = fabsf(tv.w);
                    s0 += aa[k][0]; s1 += aa[k][1]; s2 += aa[k][2]; s3 += aa[k][3];
                }
                const float i0 = __fdividef(1.f, s0), i1 = __fdividef(1.f, s1);
                const float i2 = __fdividef(1.f, s2), i3 = __fdividef(1.f, s3);
#pragma unroll
                for (int k = 0; k < 9; k++) {
                    aa[k][0] *= i0; aa[k][1] *= i1; aa[k][2] *= i2; aa[k][3] *= i3;
                }
                if (lane == 0)  { aa[0][0] = 0.f; aa[3][0] = 0.f; aa[6][0] = 0.f; }
                if (lane == 31) { aa[2][3] = 0.f; aa[5][3] = 0.f; aa[8][3] = 0.f; }
            } else {
#pragma unroll
                for (int k = 0; k < 9; k++) {
                    aa[k][0] = 0.f; aa[k][1] = 0.f; aa[k][2] = 0.f; aa[k][3] = 0.f;
                }
            }
#pragma unroll
            for (int ki = 0; ki < 3; ki++) {
                Wp[ro][ki][0] = pk(aa[ki * 3 + 0][0], aa[ki * 3 + 0][1]);
                Wp[ro][ki][1] = pk(aa[ki * 3 + 1][0], aa[ki * 3 + 1][1]);
                Wp[ro][ki][2] = pk(aa[ki * 3 + 2][0], aa[ki * 3 + 2][1]);
                Wp[ro][ki][3] = pk(aa[ki * 3 + 0][2], aa[ki * 3 + 0][3]);
                Wp[ro][ki][4] = pk(aa[ki * 3 + 1][2], aa[ki * 3 + 1][3]);
                Wp[ro][ki][5] = pk(aa[ki * 3 + 2][2], aa[ki * 3 + 2][3]);
            }
            float4 xv = make_float4(0.f, 0.f, 0.f, 0.f);
            if (rv) xv = *(const float4*)&xsp[rr * W + col0];
            if (ro == 0) y0 = xv; else y1 = xv;
            *(float4*)&buf[0][rr + 1][col0] = xv;
        }

        // pre-barrier hoist: own-row CENTER pairs only (register-only, no shfl)
        u64 p01, p02, p03, p11, p12, p13;
        p01 = pk(y0.x, y0.y); p02 = pk(y0.y, y0.z); p03 = pk(y0.z, y0.w);
        p11 = pk(y1.x, y1.y); p12 = pk(y1.y, y1.z); p13 = pk(y1.z, y1.w);
        __syncthreads();   // staging consumed + buf[0] published

        const int tn = (int)*tkt;     // next tile (written pre-barrier by tid 0)
        if (issuer && tn < NT)
            issue_prefetch_k(tn, warp, x, wgt, ws_a, xs_a, mbar);

        // ---- 8 fused steps
#pragma unroll
        for (int s = 0; s < STEPS; s++) {
            const int cb = s & 1;
            // all smem reads up front: neighbor rows (vector + clamped scalars)
            // and own-row laterals (clamped scalars; own rows are in buf too)
            const float* rowA = &buf[cb][g2][0];       // region row 2g-1
            const float* row0 = &buf[cb][g2 + 1][0];   // own row 2g
            const float* row1 = &buf[cb][g2 + 2][0];   // own row 2g+1
            const float* rowB = &buf[cb][g2 + 3][0];   // region row 2g+2
            float4 va = *(const float4*)&rowA[col0];
            const float vaL = rowA[colL], vaR = rowA[colR];
            float4 vb = *(const float4*)&rowB[col0];
            const float vbL = rowB[colL], vbR = rowB[colR];
            const float o0L = row0[colL], o0R = row0[colR];
            const float o1L = row1[colL], o1R = row1[colR];

            // chains start on register-ready center pairs (cover LDS latency)
            u64 n001 = mul2(Wp[0][1][1], p01), n023 = mul2(Wp[0][1][4], p03);
            u64 n101 = mul2(Wp[1][0][1], p01), n123 = mul2(Wp[1][0][4], p03);
            fma2(n001, Wp[0][1][2], p02); fma2(n023, Wp[0][1][3], p02);
            fma2(n101, Wp[1][0][2], p02); fma2(n123, Wp[1][0][3], p02);
            fma2(n001, Wp[0][2][1], p11); fma2(n023, Wp[0][2][4], p13);
            fma2(n101, Wp[1][1][1], p11); fma2(n123, Wp[1][1][4], p13);
            fma2(n001, Wp[0][2][2], p12); fma2(n023, Wp[0][2][3], p12);
            fma2(n101, Wp[1][1][2], p12); fma2(n123, Wp[1][1][3], p12);

            // own-row lateral pairs (scalar LDS results)
            const u64 p00 = pk(o0L, y0.x), p04 = pk(y0.w, o0R);
            const u64 p10 = pk(o1L, y1.x), p14 = pk(y1.w, o1R);
            fma2(n001, Wp[0][1][0], p00); fma2(n023, Wp[0][1][5], p04);
            fma2(n101, Wp[1][0][0], p00); fma2(n123, Wp[1][0][5], p04);
            fma2(n001, Wp[0][2][0], p10); fma2(n023, Wp[0][2][5], p14);
            fma2(n101, Wp[1][1][0], p10); fma2(n123, Wp[1][1][5], p14);

            // neighbor rows
            const u64 pA0 = pk(vaL, va.x), pA1 = pk(va.x, va.y), pA2 = pk(va.y, va.z);
            const u64 pA3 = pk(va.z, va.w), pA4 = pk(va.w, vaR);
            const u64 pB0 = pk(vbL, vb.x), pB1 = pk(vb.x, vb.y), pB2 = pk(vb.y, vb.z);
            const u64 pB3 = pk(vb.z, vb.w), pB4 = pk(vb.w, vbR);
            fma2(n001, Wp[0][0][0], pA0); fma2(n023, Wp[0][0][3], pA2);
            fma2(n101, Wp[1][2][0], pB0); fma2(n123, Wp[1][2][3], pB2);
            fma2(n001, Wp[0][0][1], pA1); fma2(n023, Wp[0][0][4], pA3);
            fma2(n101, Wp[1][2][1], pB1); fma2(n123, Wp[1][2][4], pB3);
            fma2(n001, Wp[0][0][2], pA2); fma2(n023, Wp[0][0][5], pA4);
            fma2(n101, Wp[1][2][2], pB2); fma2(n123, Wp[1][2][5], pB4);

            upk(n001, y0.x, y0.y); upk(n023, y0.z, y0.w);
            upk(n101, y1.x, y1.y); upk(n123, y1.z, y1.w);

            if (s < STEPS - 1) {
                // next step's center pairs (alu only, lat 4) then publish
                p01 = pk(y0.x, y0.y); p02 = pk(y0.y, y0.z); p03 = pk(y0.z, y0.w);
                p11 = pk(y1.x, y1.y); p12 = pk(y1.y, y1.z); p13 = pk(y1.z, y1.w);
                const int nb = cb ^ 1;
                *(float4*)&buf[nb][g2 + 1][col0] = y0;
                *(float4*)&buf[nb][g2 + 2][col0] = y1;
                __syncthreads();
            }
        }

        // ---- output: warps 4..11 hold the 16 exact rows (region rows 8..23)
        if ((unsigned)(warp - 4) < 8u) {
            float* ob = out + (size_t)img * IMG + (t0 + g2 - 8) * W + col0;
            *(float4*)ob       = y0;
            *(float4*)(ob + W) = y1;
        }
        t = tn;
        // Cross-tile safety: next prologue writes buf[0] only; the last
        // buf[0] reads were step 6, fenced by the step-6 __syncthreads.
        // Staging reuse fenced by mbar + post-prologue __syncthreads. The
        // tkt slot is rewritten only after all warps passed the barrier
        // at which they read it (7 syncthreads in between).
    }
}

extern "C" void kernel_launch(void* const* d_in, const int* in_sizes, int n_in,
                              void* d_out, int out_size)
{
    const float* x   = (const float*)d_in[0];
    const float* wgt = (const float*)d_in[1];
    float* out       = (float*)d_out;

    int sms = 152;
    cudaDeviceGetAttribute(&sms, cudaDevAttrMultiProcessorCount, 0);
    if (sms < 1) sms = 152;
    if (sms > NT) sms = NT;

    cudaFuncSetAttribute(diffusion_persist_kernel,
                         cudaFuncAttributeMaxDynamicSharedMemorySize, SMEM_TOTAL);
    reset_ticket_kernel<<<1, 1>>>();
    diffusion_persist_kernel<<<sms, 512, SMEM_TOTAL>>>(x, wgt, out);
}

// round 13
// speedup vs baseline: 1.1821x; 1.1821x over previous
#include <cuda_runtime.h>

// x:      (4, 64, 128, 128) fp32  -> 256 independent 128x128 images
// weight: (4, 576, 128, 128) fp32 -> 9 taps per channel, tap k strided by H*W
// steps = 8
//
// R9 champion (62.3us) byte-for-byte body: persistent CTAs (1/SM), 512 thr,
// V=2 (warp owns region rows 2g,2g+1 in registers), smem ping-pong, packed
// fma.rn.f32x2 stencil, clamped scalar LDS for neighbor-row laterals,
// hoisted own-row shfl+pk, mul2 chain starts, cp.async.bulk staging
// prefetched one tile ahead (10 issuer warps).
// Round 13 delta (orthogonal to the body): dynamic tile tickets via a
// global atomic (reset kernel per launch) instead of static stride —
// removes the 13-vs-14-tile quantization and per-SM speed variance from
// the makespan.

#define H      128
#define W      128
#define IMG    (H * W)
#define STEPS  8
#define TH     16
#define NT     2048
#define SROWS  34
#define RROWS  32

#define OFF_MBAR 0
#define OFF_TKT  16
#define OFF_BUF  1024
#define OFF_WS   (OFF_BUF + 2 * SROWS * W * 4)   // 1024 + 34816  = 35840
#define OFF_XS   (OFF_WS + 9 * RROWS * W * 4)    // + 147456      = 183296
#define SMEM_TOTAL (OFF_XS + RROWS * W * 4)      // + 16384       = 199680

typedef unsigned long long u64;
typedef unsigned int u32;

__device__ u32 g_ticket;

__global__ void reset_ticket_kernel() { g_ticket = 0u; }

__device__ __forceinline__ u32 s2u(const void* p) {
    u32 a;
    asm("{ .reg .u64 t; cvta.to.shared.u64 t, %1; cvt.u32.u64 %0, t; }"
        : "=r"(a) : "l"(p));
    return a;
}
__device__ __forceinline__ u64 pk(float lo, float hi) {
    u64 r; asm("mov.b64 %0, {%1,%2};" : "=l"(r) : "f"(lo), "f"(hi)); return r;
}
__device__ __forceinline__ void upk(u64 v, float& lo, float& hi) {
    asm("mov.b64 {%0,%1}, %2;" : "=f"(lo), "=f"(hi) : "l"(v));
}
__device__ __forceinline__ void fma2(u64& d, u64 a, u64 b) {
    asm("fma.rn.f32x2 %0, %1, %2, %0;" : "+l"(d) : "l"(a), "l"(b));
}
__device__ __forceinline__ u64 mul2(u64 a, u64 b) {
    u64 d; asm("mul.rn.f32x2 %0, %1, %2;" : "=l"(d) : "l"(a), "l"(b)); return d;
}
__device__ __forceinline__ float shup(float v) { return __shfl_up_sync(0xffffffffu, v, 1); }
__device__ __forceinline__ float shdn(float v) { return __shfl_down_sync(0xffffffffu, v, 1); }

__device__ __forceinline__ void mbar_wait(u32 mbar, u32 parity) {
    asm volatile(
        "{\n\t.reg .pred P;\n\t"
        "W_%=:\n\t"
        "mbarrier.try_wait.parity.shared::cta.b64 P, [%0], %1, 0x989680;\n\t"
        "@P bra.uni D_%=;\n\t"
        "bra.uni W_%=;\n\t"
        "D_%=:\n\t}"
        :: "r"(mbar), "r"(parity) : "memory");
}
__device__ __forceinline__ void bulk_g2s(u32 dst, const void* src, u32 bytes, u32 mbar) {
    asm volatile(
        "cp.async.bulk.shared::cluster.global.mbarrier::complete_tx::bytes "
        "[%0], [%1], %2, [%3];"
        :: "r"(dst), "l"(src), "r"(bytes), "r"(mbar) : "memory");
}

// Distributed prefetch: issuer k (0..8 = weight tap k, 9 = x); mbar count 10.
__device__ __forceinline__ void issue_prefetch_k(int t, int k,
                                                 const float* x, const float* wgt,
                                                 u32 ws, u32 xs, u32 mbar) {
    const int img = t >> 3;
    const int t0  = (t & 7) * TH;
    const int rlo = (t0 - 8 < 0) ? 0 : (t0 - 8);
    const int rhi = (t0 + 24 > H) ? H : (t0 + 24);
    const int nrows = rhi - rlo;
    const int droff = rlo - (t0 - 8);
    const u32 bytes = (u32)nrows * (W * 4);
    asm volatile("mbarrier.arrive.expect_tx.shared.b64 _, [%0], %1;"
                 :: "r"(mbar), "r"(bytes) : "memory");
    if (k < 9) {
        const float* src = wgt + ((size_t)(img * 9 + k) << 14) + rlo * W;
        bulk_g2s(ws + (u32)(k * RROWS + droff) * (W * 4), src, bytes, mbar);
    } else {
        bulk_g2s(xs + (u32)droff * (W * 4), x + ((size_t)img << 14) + rlo * W, bytes, mbar);
    }
}

__global__ __launch_bounds__(512, 1)
void diffusion_persist_kernel(const float* __restrict__ x,
                              const float* __restrict__ wgt,
                              float* __restrict__ out)
{
    extern __shared__ char smem[];
    float (*buf)[SROWS][W] = (float (*)[SROWS][W])(smem + OFF_BUF);
    const float* wsp = (const float*)(smem + OFF_WS);
    const float* xsp = (const float*)(smem + OFF_XS);
    volatile u32* tkt = (volatile u32*)(smem + OFF_TKT);
    const u32 mbar = s2u(smem + OFF_MBAR);
    const u32 ws_a = s2u(smem + OFF_WS);
    const u32 xs_a = s2u(smem + OFF_XS);

    const int tid  = threadIdx.x;
    const int lane = tid & 31;
    const int warp = tid >> 5;          // 0..15; owns region rows 2g, 2g+1
    const int col0 = lane << 2;
    const int g2   = warp * 2;
    // Clamped lateral columns: the clamped lanes' values hit zeroed weights.
    const int colL = (lane == 0)  ? col0     : col0 - 1;
    const int colR = (lane == 31) ? col0 + 3 : col0 + 4;
    const bool issuer = (lane == 0 && warp < 10);

    // one-time init: guard rows (region rows -1 and 32 -> zero forever), mbar
    if (tid < 128) {
        int b = tid >> 6, r = (tid >> 5) & 1;
        *(float4*)&buf[b][r ? (SROWS - 1) : 0][col0] = make_float4(0.f, 0.f, 0.f, 0.f);
    }
    if (tid == 0) {
        asm volatile("mbarrier.init.shared.b64 [%0], 10;" :: "r"(mbar) : "memory");
        *tkt = atomicAdd(&g_ticket, 1u);
    }
    __syncthreads();

    int t = (int)*tkt;
    if (issuer && t < NT) issue_prefetch_k(t, warp, x, wgt, ws_a, xs_a, mbar);
    u32 ph = 0;

    while (t < NT) {
        mbar_wait(mbar, ph); ph ^= 1u;
        if (tid == 0) *tkt = atomicAdd(&g_ticket, 1u);   // draw next tile

        const int img = t >> 3;
        const int t0  = (t & 7) * TH;

        // ---- tile prologue: weights staging -> normalized packed registers
        u64 Wp[2][3][6];
        float4 y0, y1;
#pragma unroll
        for (int ro = 0; ro < 2; ro++) {
            const int rr   = g2 + ro;
            const int grow = t0 - 8 + rr;
            const bool rv  = ((unsigned)grow < (unsigned)H);
            float aa[9][4];
            if (rv) {
                float s0 = 0.f, s1 = 0.f, s2 = 0.f, s3 = 0.f;
#pragma unroll
                for (int k = 0; k < 9; k++) {
                    float4 tv = *(const float4*)&wsp[(k * RROWS + rr) * W + col0];
                    aa[k][0] = fabsf(tv.x); aa[k][1] = fabsf(tv.y);
                    aa[k][2] = fabsf(tv.z); aa[k][3] = fabsf(tv.w);
                    s0 += aa[k][0]; s1 += aa[k][1]; s2 += aa[k][2]; s3 += aa[k][3];
                }
                const float i0 = __fdividef(1.f, s0), i1 = __fdividef(1.f, s1);
                const float i2 = __fdividef(1.f, s2), i3 = __fdividef(1.f, s3);
#pragma unroll
                for (int k = 0; k < 9; k++) {
                    aa[k][0] *= i0; aa[k][1] *= i1; aa[k][2] *= i2; aa[k][3] *= i3;
                }
                if (lane == 0)  { aa[0][0] = 0.f; aa[3][0] = 0.f; aa[6][0] = 0.f; }
                if (lane == 31) { aa[2][3] = 0.f; aa[5][3] = 0.f; aa[8][3] = 0.f; }
            } else {
#pragma unroll
                for (int k = 0; k < 9; k++) {
                    aa[k][0] = 0.f; aa[k][1] = 0.f; aa[k][2] = 0.f; aa[k][3] = 0.f;
                }
            }
#pragma unroll
            for (int ki = 0; ki < 3; ki++) {
                Wp[ro][ki][0] = pk(aa[ki * 3 + 0][0], aa[ki * 3 + 0][1]);
                Wp[ro][ki][1] = pk(aa[ki * 3 + 1][0], aa[ki * 3 + 1][1]);
                Wp[ro][ki][2] = pk(aa[ki * 3 + 2][0], aa[ki * 3 + 2][1]);
                Wp[ro][ki][3] = pk(aa[ki * 3 + 0][2], aa[ki * 3 + 0][3]);
                Wp[ro][ki][4] = pk(aa[ki * 3 + 1][2], aa[ki * 3 + 1][3]);
                Wp[ro][ki][5] = pk(aa[ki * 3 + 2][2], aa[ki * 3 + 2][3]);
            }
            float4 xv = make_float4(0.f, 0.f, 0.f, 0.f);
            if (rv) xv = *(const float4*)&xsp[rr * W + col0];
            if (ro == 0) y0 = xv; else y1 = xv;
            *(float4*)&buf[0][rr + 1][col0] = xv;
        }

        // hoisted own-row operands for step 0 (register-only; pre-barrier)
        u64 p00, p01, p02, p03, p04, p10, p11, p12, p13, p14;
        {
            const float xl0 = shup(y0.w), xr0 = shdn(y0.x);
            const float xl1 = shup(y1.w), xr1 = shdn(y1.x);
            p00 = pk(xl0, y0.x); p01 = pk(y0.x, y0.y); p02 = pk(y0.y, y0.z);
            p03 = pk(y0.z, y0.w); p04 = pk(y0.w, xr0);
            p10 = pk(xl1, y1.x); p11 = pk(y1.x, y1.y); p12 = pk(y1.y, y1.z);
            p13 = pk(y1.z, y1.w); p14 = pk(y1.w, xr1);
        }
        __syncthreads();   // staging consumed + buf[0] published + tkt visible

        const int tn = (int)*tkt;   // next tile (ticket drawn pre-barrier)
        if (issuer && tn < NT)
            issue_prefetch_k(tn, warp, x, wgt, ws_a, xs_a, mbar);

        // ---- 8 fused steps (R9 body, unmodified)
#pragma unroll
        for (int s = 0; s < STEPS; s++) {
            const int cb = s & 1;
            // neighbor rows: vector + parallel lateral scalars (no shfl chain)
            const float* rowA = &buf[cb][g2][0];
            const float* rowB = &buf[cb][g2 + 3][0];
            float4 va = *(const float4*)&rowA[col0];
            const float vaL = rowA[colL], vaR = rowA[colR];
            float4 vb = *(const float4*)&rowB[col0];
            const float vbL = rowB[colL], vbR = rowB[colR];

            const u64 pA0 = pk(vaL, va.x), pA1 = pk(va.x, va.y), pA2 = pk(va.y, va.z);
            const u64 pA3 = pk(va.z, va.w), pA4 = pk(va.w, vaR);
            const u64 pB0 = pk(vbL, vb.x), pB1 = pk(vb.x, vb.y), pB2 = pk(vb.y, vb.z);
            const u64 pB3 = pk(vb.z, vb.w), pB4 = pk(vb.w, vbR);

            // chains start on own-row operands (ready at loop top)
            u64 n001 = mul2(Wp[0][1][0], p00), n023 = mul2(Wp[0][1][3], p02);
            u64 n101 = mul2(Wp[1][0][0], p00), n123 = mul2(Wp[1][0][3], p02);
            fma2(n001, Wp[0][1][1], p01); fma2(n023, Wp[0][1][4], p03);
            fma2(n101, Wp[1][0][1], p01); fma2(n123, Wp[1][0][4], p03);
            fma2(n001, Wp[0][1][2], p02); fma2(n023, Wp[0][1][5], p04);
            fma2(n101, Wp[1][0][2], p02); fma2(n123, Wp[1][0][5], p04);

            fma2(n001, Wp[0][2][0], p10); fma2(n023, Wp[0][2][3], p12);
            fma2(n101, Wp[1][1][0], p10); fma2(n123, Wp[1][1][3], p12);
            fma2(n001, Wp[0][2][1], p11); fma2(n023, Wp[0][2][4], p13);
            fma2(n101, Wp[1][1][1], p11); fma2(n123, Wp[1][1][4], p13);
            fma2(n001, Wp[0][2][2], p12); fma2(n023, Wp[0][2][5], p14);
            fma2(n101, Wp[1][1][2], p12); fma2(n123, Wp[1][1][5], p14);

            fma2(n001, Wp[0][0][0], pA0); fma2(n023, Wp[0][0][3], pA2);
            fma2(n101, Wp[1][2][0], pB0); fma2(n123, Wp[1][2][3], pB2);
            fma2(n001, Wp[0][0][1], pA1); fma2(n023, Wp[0][0][4], pA3);
            fma2(n101, Wp[1][2][1], pB1); fma2(n123, Wp[1][2][4], pB3);
            fma2(n001, Wp[0][0][2], pA2); fma2(n023, Wp[0][0][5], pA4);
            fma2(n101, Wp[1][2][2], pB2); fma2(n123, Wp[1][2][5], pB4);

            upk(n001, y0.x, y0.y); upk(n023, y0.z, y0.w);
            upk(n101, y1.x, y1.y); upk(n123, y1.z, y1.w);

            if (s < STEPS - 1) {
                // hoist next step's own-row operands BEFORE the barrier
                const float xl0 = shup(y0.w), xr0 = shdn(y0.x);
                const float xl1 = shup(y1.w), xr1 = shdn(y1.x);
                p00 = pk(xl0, y0.x); p01 = pk(y0.x, y0.y); p02 = pk(y0.y, y0.z);
                p03 = pk(y0.z, y0.w); p04 = pk(y0.w, xr0);
                p10 = pk(xl1, y1.x); p11 = pk(y1.x, y1.y); p12 = pk(y1.y, y1.z);
                p13 = pk(y1.z, y1.w); p14 = pk(y1.w, xr1);

                const int nb = cb ^ 1;
                *(float4*)&buf[nb][g2 + 1][col0] = y0;
                *(float4*)&buf[nb][g2 + 2][col0] = y1;
                __syncthreads();
            }
        }

        // ---- output: warps 4..11 hold the 16 exact rows (region rows 8..23)
        if ((unsigned)(warp - 4) < 8u) {
            float* ob = out + (size_t)img * IMG + (t0 + g2 - 8) * W + col0;
            *(float4*)ob       = y0;
            *(float4*)(ob + W) = y1;
        }
        t = tn;
        // Cross-tile safety: next prologue writes buf[0] only; last buf[0]
        // reads were step 6, fenced by the step-6 __syncthreads. Staging
        // reuse fenced by mbar + post-prologue __syncthreads. tkt is
        // rewritten only after the barrier at which all warps read it.
    }
}

extern "C" void kernel_launch(void* const* d_in, const int* in_sizes, int n_in,
                              void* d_out, int out_size)
{
    const float* x   = (const float*)d_in[0];
    const float* wgt = (const float*)d_in[1];
    float* out       = (float*)d_out;

    int sms = 152;
    cudaDeviceGetAttribute(&sms, cudaDevAttrMultiProcessorCount, 0);
    if (sms < 1) sms = 152;
    if (sms > NT) sms = NT;

    cudaFuncSetAttribute(diffusion_persist_kernel,
                         cudaFuncAttributeMaxDynamicSharedMemorySize, SMEM_TOTAL);
    reset_ticket_kernel<<<1, 1>>>();
    diffusion_persist_kernel<<<sms, 512, SMEM_TOTAL>>>(x, wgt, out);
}

// round 14
// speedup vs baseline: 1.3358x; 1.1301x over previous
#include <cuda_runtime.h>

// x:      (4, 64, 128, 128) fp32  -> 256 independent 128x128 images
// weight: (4, 576, 128, 128) fp32 -> 9 taps per channel, tap k strided by H*W
// steps = 8
//
// R9 champion (62.3us) body, static stride, 1 CTA/SM, 512 thr, V=2,
// smem ping-pong, packed fma.rn.f32x2, clamped scalar LDS laterals,
// hoisted own-row shfl+pk, cp.async.bulk staging prefetch (10 issuers).
// Round 14 delta: shrinking-band work elision. Warp g only computes steps
// n <= nmax_g = min(2g+1, 31-2g) (1-based): out-of-band rows are garbage
// that feeds only garbage (proven by the halo-validity argument), so the
// compute+publish is skipped while barriers are kept. Cuts step-loop
// instructions 25%, perfectly balanced across the 4 SMSPs (24/32 each).

#define H      128
#define W      128
#define IMG    (H * W)
#define STEPS  8
#define TH     16
#define NT     2048
#define SROWS  34
#define RROWS  32

#define OFF_MBAR 0
#define OFF_BUF  1024
#define OFF_WS   (OFF_BUF + 2 * SROWS * W * 4)   // 1024 + 34816  = 35840
#define OFF_XS   (OFF_WS + 9 * RROWS * W * 4)    // + 147456      = 183296
#define SMEM_TOTAL (OFF_XS + RROWS * W * 4)      // + 16384       = 199680

typedef unsigned long long u64;
typedef unsigned int u32;

__device__ __forceinline__ u32 s2u(const void* p) {
    u32 a;
    asm("{ .reg .u64 t; cvta.to.shared.u64 t, %1; cvt.u32.u64 %0, t; }"
        : "=r"(a) : "l"(p));
    return a;
}
__device__ __forceinline__ u64 pk(float lo, float hi) {
    u64 r; asm("mov.b64 %0, {%1,%2};" : "=l"(r) : "f"(lo), "f"(hi)); return r;
}
__device__ __forceinline__ void upk(u64 v, float& lo, float& hi) {
    asm("mov.b64 {%0,%1}, %2;" : "=f"(lo), "=f"(hi) : "l"(v));
}
__device__ __forceinline__ void fma2(u64& d, u64 a, u64 b) {
    asm("fma.rn.f32x2 %0, %1, %2, %0;" : "+l"(d) : "l"(a), "l"(b));
}
__device__ __forceinline__ u64 mul2(u64 a, u64 b) {
    u64 d; asm("mul.rn.f32x2 %0, %1, %2;" : "=l"(d) : "l"(a), "l"(b)); return d;
}
__device__ __forceinline__ float shup(float v) { return __shfl_up_sync(0xffffffffu, v, 1); }
__device__ __forceinline__ float shdn(float v) { return __shfl_down_sync(0xffffffffu, v, 1); }

__device__ __forceinline__ void mbar_wait(u32 mbar, u32 parity) {
    asm volatile(
        "{\n\t.reg .pred P;\n\t"
        "W_%=:\n\t"
        "mbarrier.try_wait.parity.shared::cta.b64 P, [%0], %1, 0x989680;\n\t"
        "@P bra.uni D_%=;\n\t"
        "bra.uni W_%=;\n\t"
        "D_%=:\n\t}"
        :: "r"(mbar), "r"(parity) : "memory");
}
__device__ __forceinline__ void bulk_g2s(u32 dst, const void* src, u32 bytes, u32 mbar) {
    asm volatile(
        "cp.async.bulk.shared::cluster.global.mbarrier::complete_tx::bytes "
        "[%0], [%1], %2, [%3];"
        :: "r"(dst), "l"(src), "r"(bytes), "r"(mbar) : "memory");
}

// Distributed prefetch: issuer k (0..8 = weight tap k, 9 = x); mbar count 10.
__device__ __forceinline__ void issue_prefetch_k(int t, int k,
                                                 const float* x, const float* wgt,
                                                 u32 ws, u32 xs, u32 mbar) {
    const int img = t >> 3;
    const int t0  = (t & 7) * TH;
    const int rlo = (t0 - 8 < 0) ? 0 : (t0 - 8);
    const int rhi = (t0 + 24 > H) ? H : (t0 + 24);
    const int nrows = rhi - rlo;
    const int droff = rlo - (t0 - 8);
    const u32 bytes = (u32)nrows * (W * 4);
    asm volatile("mbarrier.arrive.expect_tx.shared.b64 _, [%0], %1;"
                 :: "r"(mbar), "r"(bytes) : "memory");
    if (k < 9) {
        const float* src = wgt + ((size_t)(img * 9 + k) << 14) + rlo * W;
        bulk_g2s(ws + (u32)(k * RROWS + droff) * (W * 4), src, bytes, mbar);
    } else {
        bulk_g2s(xs + (u32)droff * (W * 4), x + ((size_t)img << 14) + rlo * W, bytes, mbar);
    }
}

__global__ __launch_bounds__(512, 1)
void diffusion_persist_kernel(const float* __restrict__ x,
                              const float* __restrict__ wgt,
                              float* __restrict__ out)
{
    extern __shared__ char smem[];
    float (*buf)[SROWS][W] = (float (*)[SROWS][W])(smem + OFF_BUF);
    const float* wsp = (const float*)(smem + OFF_WS);
    const float* xsp = (const float*)(smem + OFF_XS);
    const u32 mbar = s2u(smem + OFF_MBAR);
    const u32 ws_a = s2u(smem + OFF_WS);
    const u32 xs_a = s2u(smem + OFF_XS);

    const int tid  = threadIdx.x;
    const int lane = tid & 31;
    const int warp = tid >> 5;          // 0..15; owns region rows 2g, 2g+1
    const int col0 = lane << 2;
    const int g2   = warp * 2;
    // Clamped lateral columns: the clamped lanes' values hit zeroed weights.
    const int colL = (lane == 0)  ? col0     : col0 - 1;
    const int colR = (lane == 31) ? col0 + 3 : col0 + 4;
    const bool issuer = (lane == 0 && warp < 10);
    // shrinking-band bound: compute step index s (0-based) iff s < nmax
    const int nmax = (g2 + 1 < 31 - g2) ? (g2 + 1) : (31 - g2);

    // one-time init: guard rows (region rows -1 and 32 -> zero forever), mbar
    if (tid < 128) {
        int b = tid >> 6, r = (tid >> 5) & 1;
        *(float4*)&buf[b][r ? (SROWS - 1) : 0][col0] = make_float4(0.f, 0.f, 0.f, 0.f);
    }
    if (tid == 0) {
        asm volatile("mbarrier.init.shared.b64 [%0], 10;" :: "r"(mbar) : "memory");
    }
    __syncthreads();

    int t = blockIdx.x;
    const int stride = gridDim.x;
    if (issuer && t < NT) issue_prefetch_k(t, warp, x, wgt, ws_a, xs_a, mbar);
    u32 ph = 0;

    for (; t < NT; t += stride) {
        mbar_wait(mbar, ph); ph ^= 1u;

        const int img = t >> 3;
        const int t0  = (t & 7) * TH;

        // ---- tile prologue: weights staging -> normalized packed registers
        u64 Wp[2][3][6];
        float4 y0, y1;
#pragma unroll
        for (int ro = 0; ro < 2; ro++) {
            const int rr   = g2 + ro;
            const int grow = t0 - 8 + rr;
            const bool rv  = ((unsigned)grow < (unsigned)H);
            float aa[9][4];
            if (rv) {
                float s0 = 0.f, s1 = 0.f, s2 = 0.f, s3 = 0.f;
#pragma unroll
                for (int k = 0; k < 9; k++) {
                    float4 tv = *(const float4*)&wsp[(k * RROWS + rr) * W + col0];
                    aa[k][0] = fabsf(tv.x); aa[k][1] = fabsf(tv.y);
                    aa[k][2] = fabsf(tv.z); aa[k][3] = fabsf(tv.w);
                    s0 += aa[k][0]; s1 += aa[k][1]; s2 += aa[k][2]; s3 += aa[k][3];
                }
                const float i0 = __fdividef(1.f, s0), i1 = __fdividef(1.f, s1);
                const float i2 = __fdividef(1.f, s2), i3 = __fdividef(1.f, s3);
#pragma unroll
                for (int k = 0; k < 9; k++) {
                    aa[k][0] *= i0; aa[k][1] *= i1; aa[k][2] *= i2; aa[k][3] *= i3;
                }
                if (lane == 0)  { aa[0][0] = 0.f; aa[3][0] = 0.f; aa[6][0] = 0.f; }
                if (lane == 31) { aa[2][3] = 0.f; aa[5][3] = 0.f; aa[8][3] = 0.f; }
            } else {
#pragma unroll
                for (int k = 0; k < 9; k++) {
                    aa[k][0] = 0.f; aa[k][1] = 0.f; aa[k][2] = 0.f; aa[k][3] = 0.f;
                }
            }
#pragma unroll
            for (int ki = 0; ki < 3; ki++) {
                Wp[ro][ki][0] = pk(aa[ki * 3 + 0][0], aa[ki * 3 + 0][1]);
                Wp[ro][ki][1] = pk(aa[ki * 3 + 1][0], aa[ki * 3 + 1][1]);
                Wp[ro][ki][2] = pk(aa[ki * 3 + 2][0], aa[ki * 3 + 2][1]);
                Wp[ro][ki][3] = pk(aa[ki * 3 + 0][2], aa[ki * 3 + 0][3]);
                Wp[ro][ki][4] = pk(aa[ki * 3 + 1][2], aa[ki * 3 + 1][3]);
                Wp[ro][ki][5] = pk(aa[ki * 3 + 2][2], aa[ki * 3 + 2][3]);
            }
            float4 xv = make_float4(0.f, 0.f, 0.f, 0.f);
            if (rv) xv = *(const float4*)&xsp[rr * W + col0];
            if (ro == 0) y0 = xv; else y1 = xv;
            *(float4*)&buf[0][rr + 1][col0] = xv;
        }

        // hoisted own-row operands for step 0 (register-only; pre-barrier)
        u64 p00, p01, p02, p03, p04, p10, p11, p12, p13, p14;
        {
            const float xl0 = shup(y0.w), xr0 = shdn(y0.x);
            const float xl1 = shup(y1.w), xr1 = shdn(y1.x);
            p00 = pk(xl0, y0.x); p01 = pk(y0.x, y0.y); p02 = pk(y0.y, y0.z);
            p03 = pk(y0.z, y0.w); p04 = pk(y0.w, xr0);
            p10 = pk(xl1, y1.x); p11 = pk(y1.x, y1.y); p12 = pk(y1.y, y1.z);
            p13 = pk(y1.z, y1.w); p14 = pk(y1.w, xr1);
        }
        __syncthreads();   // staging consumed + buf[0] published

        // prefetch next tile (distributed; overlaps the 8-step loop)
        if (issuer && t + stride < NT)
            issue_prefetch_k(t + stride, warp, x, wgt, ws_a, xs_a, mbar);

        // ---- 8 fused steps with shrinking-band elision
#pragma unroll
        for (int s = 0; s < STEPS; s++) {
            if (s < nmax) {
                const int cb = s & 1;
                const float* rowA = &buf[cb][g2][0];
                const float* rowB = &buf[cb][g2 + 3][0];
                float4 va = *(const float4*)&rowA[col0];
                const float vaL = rowA[colL], vaR = rowA[colR];
                float4 vb = *(const float4*)&rowB[col0];
                const float vbL = rowB[colL], vbR = rowB[colR];

                const u64 pA0 = pk(vaL, va.x), pA1 = pk(va.x, va.y), pA2 = pk(va.y, va.z);
                const u64 pA3 = pk(va.z, va.w), pA4 = pk(va.w, vaR);
                const u64 pB0 = pk(vbL, vb.x), pB1 = pk(vb.x, vb.y), pB2 = pk(vb.y, vb.z);
                const u64 pB3 = pk(vb.z, vb.w), pB4 = pk(vb.w, vbR);

                u64 n001 = mul2(Wp[0][1][0], p00), n023 = mul2(Wp[0][1][3], p02);
                u64 n101 = mul2(Wp[1][0][0], p00), n123 = mul2(Wp[1][0][3], p02);
                fma2(n001, Wp[0][1][1], p01); fma2(n023, Wp[0][1][4], p03);
                fma2(n101, Wp[1][0][1], p01); fma2(n123, Wp[1][0][4], p03);
                fma2(n001, Wp[0][1][2], p02); fma2(n023, Wp[0][1][5], p04);
                fma2(n101, Wp[1][0][2], p02); fma2(n123, Wp[1][0][5], p04);

                fma2(n001, Wp[0][2][0], p10); fma2(n023, Wp[0][2][3], p12);
                fma2(n101, Wp[1][1][0], p10); fma2(n123, Wp[1][1][3], p12);
                fma2(n001, Wp[0][2][1], p11); fma2(n023, Wp[0][2][4], p13);
                fma2(n101, Wp[1][1][1], p11); fma2(n123, Wp[1][1][4], p13);
                fma2(n001, Wp[0][2][2], p12); fma2(n023, Wp[0][2][5], p14);
                fma2(n101, Wp[1][1][2], p12); fma2(n123, Wp[1][1][5], p14);

                fma2(n001, Wp[0][0][0], pA0); fma2(n023, Wp[0][0][3], pA2);
                fma2(n101, Wp[1][2][0], pB0); fma2(n123, Wp[1][2][3], pB2);
                fma2(n001, Wp[0][0][1], pA1); fma2(n023, Wp[0][0][4], pA3);
                fma2(n101, Wp[1][2][1], pB1); fma2(n123, Wp[1][2][4], pB3);
                fma2(n001, Wp[0][0][2], pA2); fma2(n023, Wp[0][0][5], pA4);
                fma2(n101, Wp[1][2][2], pB2); fma2(n123, Wp[1][2][5], pB4);

                upk(n001, y0.x, y0.y); upk(n023, y0.z, y0.w);
                upk(n101, y1.x, y1.y); upk(n123, y1.z, y1.w);

                if (s < STEPS - 1) {
                    // hoist next step's own-row operands BEFORE the barrier
                    const float xl0 = shup(y0.w), xr0 = shdn(y0.x);
                    const float xl1 = shup(y1.w), xr1 = shdn(y1.x);
                    p00 = pk(xl0, y0.x); p01 = pk(y0.x, y0.y); p02 = pk(y0.y, y0.z);
                    p03 = pk(y0.z, y0.w); p04 = pk(y0.w, xr0);
                    p10 = pk(xl1, y1.x); p11 = pk(y1.x, y1.y); p12 = pk(y1.y, y1.z);
                    p13 = pk(y1.z, y1.w); p14 = pk(y1.w, xr1);

                    const int nb = cb ^ 1;
                    *(float4*)&buf[nb][g2 + 1][col0] = y0;
                    *(float4*)&buf[nb][g2 + 2][col0] = y1;
                }
            }
            if (s < STEPS - 1) __syncthreads();
        }

        // ---- output: warps 4..11 hold the 16 exact rows (region rows 8..23)
        if ((unsigned)(warp - 4) < 8u) {
            float* ob = out + (size_t)img * IMG + (t0 + g2 - 8) * W + col0;
            *(float4*)ob       = y0;
            *(float4*)(ob + W) = y1;
        }
        // Cross-tile safety unchanged from R9: next prologue writes buf[0]
        // only; last meaningful buf[0] reads were step 6, fenced by the
        // step-6 __syncthreads (all warps still arrive at every barrier).
        // Staging reuse fenced by mbar + post-prologue __syncthreads.
    }
}

extern "C" void kernel_launch(void* const* d_in, const int* in_sizes, int n_in,
                              void* d_out, int out_size)
{
    const float* x   = (const float*)d_in[0];
    const float* wgt = (const float*)d_in[1];
    float* out       = (float*)d_out;

    int sms = 152;
    cudaDeviceGetAttribute(&sms, cudaDevAttrMultiProcessorCount, 0);
    if (sms < 1) sms = 152;
    if (sms > NT) sms = NT;

    cudaFuncSetAttribute(diffusion_persist_kernel,
                         cudaFuncAttributeMaxDynamicSharedMemorySize, SMEM_TOTAL);
    diffusion_persist_kernel<<<sms, 512, SMEM_TOTAL>>>(x, wgt, out);
}